// round 7
// baseline (speedup 1.0000x reference)
#include <cuda_runtime.h>
#include <cstdint>

#define N_TOK 4096
#define HDIM  1024
#define NEXP  16
#define TM 128
#define TN 128
#define TK 32
#define NT 8                 // HDIM / TN
#define KTILES (HDIM / TK)   // 32
#define SLD 36
#define STAGE_FLOATS ((TM + TN) * SLD)
#define STAGE_BYTES  (STAGE_FLOATS * 4)
#define SMEM_TOTAL   (2 * STAGE_BYTES)   // 73728 -> 2 CTAs/SM fits 227KB

__device__ int   g_top2_idx[N_TOK * 2];
__device__ float g_top2_w[N_TOK * 2];
__device__ int   g_slot[N_TOK * 2];
__device__ int   g_counts[NEXP];
__device__ int   g_offsets[NEXP];
__device__ int   g_fill[NEXP];
__device__ int   g_mtp[NEXP + 1];
__device__ int   g_units_total;
__device__ int   g_unit_ctr;
__device__ int   g_tok[2 * N_TOK];
__device__ float g_staging[(size_t)2 * N_TOK * HDIM];

// ---------- gate: 16 tokens/block, warp e keeps gate_w[e] in registers ----------
__global__ void __launch_bounds__(512)
gate_kernel(const float* __restrict__ tokens, const float* __restrict__ gate_w) {
    const int w = threadIdx.x >> 5;       // expert id
    const int lane = threadIdx.x & 31;
    const int tok0 = blockIdx.x * 16;

    float4 wreg[8];
    const float4* gw = (const float4*)(gate_w + (size_t)w * HDIM);
#pragma unroll
    for (int i = 0; i < 8; i++) wreg[i] = gw[lane + i * 32];

    __shared__ float lg[16][NEXP + 1];

    for (int t = 0; t < 16; t++) {
        const float4* x = (const float4*)(tokens + (size_t)(tok0 + t) * HDIM);
        float s = 0.f;
#pragma unroll
        for (int i = 0; i < 8; i++) {
            float4 a = x[lane + i * 32];
            s += a.x * wreg[i].x + a.y * wreg[i].y + a.z * wreg[i].z + a.w * wreg[i].w;
        }
#pragma unroll
        for (int o = 16; o; o >>= 1) s += __shfl_xor_sync(0xffffffffu, s, o);
        if (lane == 0) lg[t][w] = s;
    }
    __syncthreads();

    if (threadIdx.x < 16) {
        const int t = threadIdx.x;
        const int n = tok0 + t;
        float mx = lg[t][0];
#pragma unroll
        for (int e = 1; e < NEXP; e++) mx = fmaxf(mx, lg[t][e]);
        float p[NEXP], sum = 0.f;
#pragma unroll
        for (int e = 0; e < NEXP; e++) { p[e] = expf(lg[t][e] - mx); sum += p[e]; }
        float b1 = -1.f, b2 = -1.f; int i1 = 0, i2 = 0;
#pragma unroll
        for (int e = 0; e < NEXP; e++) {
            float v = p[e];
            if (v > b1)      { b2 = b1; i2 = i1; b1 = v; i1 = e; }
            else if (v > b2) { b2 = v;  i2 = e; }
        }
        float inv = 1.f / sum;
        g_top2_idx[n * 2 + 0] = i1;
        g_top2_idx[n * 2 + 1] = i2;
        g_top2_w[n * 2 + 0] = b1 * inv;
        g_top2_w[n * 2 + 1] = b2 * inv;
    }
}

// ---------- count + scan (single block) ----------
__global__ void __launch_bounds__(512)
count_scan_kernel() {
    __shared__ int hist[16][NEXP];
    const int tid = threadIdx.x, wid = tid >> 5;
    if (tid < 16 * NEXP) ((int*)hist)[tid] = 0;
    __syncthreads();
    for (int i = tid; i < 2 * N_TOK; i += 512)
        atomicAdd(&hist[wid][g_top2_idx[i]], 1);
    __syncthreads();
    if (tid < NEXP) {
        int c = 0;
#pragma unroll
        for (int r = 0; r < 16; r++) c += hist[r][tid];
        g_counts[tid] = c;
        g_fill[tid] = 0;
    }
    __syncthreads();
    if (tid == 0) {
        int acc = 0, accm = 0;
#pragma unroll
        for (int e = 0; e < NEXP; e++) {
            g_offsets[e] = acc; acc += g_counts[e];
            g_mtp[e] = accm;    accm += (g_counts[e] + TM - 1) / TM;
        }
        g_mtp[NEXP] = accm;
        g_units_total = accm * NT;
        g_unit_ctr = 0;
    }
}

// ---------- scatter: warp-aggregated atomics ----------
__global__ void scatter_kernel() {
    const int i = blockIdx.x * 256 + threadIdx.x;   // slot id in [0, 8192)
    const int lane = threadIdx.x & 31;
    const int e = g_top2_idx[i];
    unsigned mask = __match_any_sync(0xffffffffu, e);
    int leader = __ffs(mask) - 1;
    int lrank = __popc(mask & ((1u << lane) - 1));
    int base = 0;
    if (lane == leader) base = atomicAdd(&g_fill[e], __popc(mask));
    base = __shfl_sync(0xffffffffu, base, leader);
    int o = g_offsets[e] + base + lrank;
    g_tok[o] = i >> 1;
    g_slot[i] = o;
}

// ---------- persistent tf32 grouped GEMM, occupancy 2 ----------
__device__ __forceinline__ void cpa16(uint32_t dst, const float* src, bool valid) {
    int sz = valid ? 16 : 0;
    asm volatile("cp.async.cg.shared.global [%0], [%1], 16, %2;\n"
                 :: "r"(dst), "l"(src), "r"(sz));
}

__global__ void __launch_bounds__(256, 2)
moe_gemm_kernel(const float* __restrict__ tokens,
                const float* __restrict__ expert_w,
                const float* __restrict__ expert_b) {
    extern __shared__ float smem[];
    __shared__ int uinfo[6];
    const uint32_t sbase = (uint32_t)__cvta_generic_to_shared(smem);

    const int tid  = threadIdx.x;
    const int lane = tid & 31;
    const int warp = tid >> 5;
    const int g    = lane >> 2;
    const int c    = lane & 3;
    const int wm0  = (warp & 3) * 32;
    const int wn0  = (warp >> 2) * 64;

    for (;;) {
        if (tid == 0) {
            int u = atomicAdd(&g_unit_ctr, 1);
            uinfo[0] = u;
            if (u < g_units_total) {
                int nt = u & (NT - 1);
                int mu = u >> 3;
                int e = 0;
                while (mu >= g_mtp[e + 1]) e++;
                uinfo[1] = e;
                uinfo[2] = (mu - g_mtp[e]) * TM;
                uinfo[3] = nt * TN;
                uinfo[4] = g_offsets[e];
                uinfo[5] = g_counts[e];
            }
        }
        __syncthreads();
        if (uinfo[0] >= g_units_total) break;
        const int e = uinfo[1], m0 = uinfo[2], n0 = uinfo[3];
        const int base = uinfo[4], cnt = uinfo[5];

        // per-thread global source setup: 4x16B for A, 4x16B for B
        const float* aSrc[4];
        const float* bSrc[4];
        bool aV[4];
        uint32_t offA[4], offB[4];
#pragma unroll
        for (int i = 0; i < 4; i++) {
            int slot = tid + i * 256;
            int r  = slot >> 3;
            int c4 = slot & 7;
            offA[i] = (uint32_t)((r * SLD + c4 * 4) * 4);
            offB[i] = (uint32_t)(TM * SLD * 4) + offA[i];
            int m = m0 + r;
            if (m < cnt) {
                aSrc[i] = tokens + (size_t)g_tok[base + m] * HDIM + c4 * 4;
                aV[i] = true;
            } else { aSrc[i] = tokens; aV[i] = false; }
            bSrc[i] = expert_w + (size_t)e * HDIM * HDIM + (size_t)(n0 + r) * HDIM + c4 * 4;
        }

        auto issue_copy = [&](int kt, int stage) {
            uint32_t sb = sbase + (uint32_t)stage * STAGE_BYTES;
            int ko = kt * TK;
#pragma unroll
            for (int i = 0; i < 4; i++) {
                cpa16(sb + offA[i], aSrc[i] + ko, aV[i]);
                cpa16(sb + offB[i], bSrc[i] + ko, true);
            }
        };

        float acc[2][8][4];
#pragma unroll
        for (int mi = 0; mi < 2; mi++)
#pragma unroll
            for (int ni = 0; ni < 8; ni++)
#pragma unroll
                for (int r = 0; r < 4; r++) acc[mi][ni][r] = 0.f;

        issue_copy(0, 0);
        asm volatile("cp.async.commit_group;\n" ::: "memory");

        for (int kt = 0; kt < KTILES; kt++) {
            const int cs = kt & 1;
            if (kt + 1 < KTILES) {
                issue_copy(kt + 1, cs ^ 1);
                asm volatile("cp.async.commit_group;\n" ::: "memory");
                asm volatile("cp.async.wait_group 1;\n" ::: "memory");
            } else {
                asm volatile("cp.async.wait_group 0;\n" ::: "memory");
            }
            __syncthreads();

            const float* sA = smem + cs * STAGE_FLOATS;
            const float* sB = sA + TM * SLD;

#pragma unroll
            for (int ks = 0; ks < 4; ks++) {
                const int k0 = ks * 8;
                uint32_t a0[2], a1[2], a2[2], a3[2];
#pragma unroll
                for (int mi = 0; mi < 2; mi++) {
                    const float* ap = sA + (wm0 + mi * 16 + g) * SLD + k0 + c;
                    a0[mi] = __float_as_uint(ap[0]);
                    a1[mi] = __float_as_uint(ap[8 * SLD]);
                    a2[mi] = __float_as_uint(ap[4]);
                    a3[mi] = __float_as_uint(ap[8 * SLD + 4]);
                }
#pragma unroll
                for (int ni = 0; ni < 8; ni++) {
                    const float* bp = sB + (wn0 + ni * 8 + g) * SLD + k0 + c;
                    uint32_t b0 = __float_as_uint(bp[0]);
                    uint32_t b1 = __float_as_uint(bp[4]);
#pragma unroll
                    for (int mi = 0; mi < 2; mi++) {
                        float* d = acc[mi][ni];
                        asm volatile(
                            "mma.sync.aligned.m16n8k8.row.col.f32.tf32.tf32.f32 "
                            "{%0,%1,%2,%3},{%4,%5,%6,%7},{%8,%9},{%0,%1,%2,%3};\n"
                            : "+f"(d[0]), "+f"(d[1]), "+f"(d[2]), "+f"(d[3])
                            : "r"(a0[mi]), "r"(a1[mi]), "r"(a2[mi]), "r"(a3[mi]),
                              "r"(b0), "r"(b1));
                    }
                }
            }
            __syncthreads();
        }

        // epilogue: relu(acc + bias) -> staging
        float2 bias2[8];
#pragma unroll
        for (int ni = 0; ni < 8; ni++) {
            int n = n0 + wn0 + ni * 8 + 2 * c;
            bias2[ni] = *(const float2*)(expert_b + (size_t)e * HDIM + n);
        }
#pragma unroll
        for (int mi = 0; mi < 2; mi++) {
#pragma unroll
            for (int half = 0; half < 2; half++) {
                int m = m0 + wm0 + mi * 16 + g + half * 8;
                if (m < cnt) {
                    float* orow = g_staging + (size_t)(base + m) * HDIM + n0 + wn0 + 2 * c;
#pragma unroll
                    for (int ni = 0; ni < 8; ni++) {
                        float v0 = fmaxf(acc[mi][ni][half * 2 + 0] + bias2[ni].x, 0.f);
                        float v1 = fmaxf(acc[mi][ni][half * 2 + 1] + bias2[ni].y, 0.f);
                        *(float2*)(orow + ni * 8) = make_float2(v0, v1);
                    }
                }
            }
        }
        __syncthreads();   // protect uinfo/smem reuse
    }
}

// ---------- combine ----------
__global__ void combine_kernel(float* __restrict__ out) {
    const int n = blockIdx.x;
    const int s0 = g_slot[n * 2], s1 = g_slot[n * 2 + 1];
    const float w0 = g_top2_w[n * 2], w1 = g_top2_w[n * 2 + 1];
    const float4* a = (const float4*)(g_staging + (size_t)s0 * HDIM);
    const float4* b = (const float4*)(g_staging + (size_t)s1 * HDIM);
    float4* o = (float4*)(out + (size_t)n * HDIM);
    for (int i = threadIdx.x; i < HDIM / 4; i += blockDim.x) {
        float4 x = a[i], y = b[i];
        o[i] = make_float4(w0 * x.x + w1 * y.x, w0 * x.y + w1 * y.y,
                           w0 * x.z + w1 * y.z, w0 * x.w + w1 * y.w);
    }
}

extern "C" void kernel_launch(void* const* d_in, const int* in_sizes, int n_in,
                              void* d_out, int out_size) {
    const float* tokens   = (const float*)d_in[0];
    const float* gate_w   = (const float*)d_in[1];
    const float* expert_w = (const float*)d_in[2];
    const float* expert_b = (const float*)d_in[3];
    float* out = (float*)d_out;

    cudaFuncSetAttribute(moe_gemm_kernel,
                         cudaFuncAttributeMaxDynamicSharedMemorySize, SMEM_TOTAL);

    gate_kernel<<<N_TOK / 16, 512>>>(tokens, gate_w);
    count_scan_kernel<<<1, 512>>>();
    scatter_kernel<<<2 * N_TOK / 256, 256>>>();
    moe_gemm_kernel<<<296, 256, SMEM_TOTAL>>>(tokens, expert_w, expert_b);
    combine_kernel<<<N_TOK, 256>>>(out);
}

// round 8
// speedup vs baseline: 1.1095x; 1.1095x over previous
#include <cuda_runtime.h>
#include <cstdint>

#define N_TOK 4096
#define HDIM  1024
#define NEXP  16
#define TM 128
#define TN 256
#define TK 32
#define NT 4                 // HDIM / TN
#define KTILES (HDIM / TK)   // 32
#define SLD 36
#define A_FLOATS (TM * SLD)                 // 4608
#define STAGE_FLOATS ((TM + TN) * SLD)      // 13824
#define STAGE_BYTES  (STAGE_FLOATS * 4)     // 55296
#define NSTAGE 3
#define SMEM_TOTAL (NSTAGE * STAGE_BYTES)   // 165888

__device__ int   g_top2_idx[N_TOK * 2];
__device__ float g_top2_w[N_TOK * 2];
__device__ int   g_slot[N_TOK * 2];
__device__ int   g_counts[NEXP];
__device__ int   g_offsets[NEXP];
__device__ int   g_fill[NEXP];
__device__ int   g_mtp[NEXP + 1];
__device__ int   g_units_total;
__device__ int   g_unit_ctr;
__device__ int   g_tok[2 * N_TOK];
__device__ float g_staging[(size_t)2 * N_TOK * HDIM];

// ---------- gate: 16 tokens/block, warp e keeps gate_w[e] in registers ----------
__global__ void __launch_bounds__(512)
gate_kernel(const float* __restrict__ tokens, const float* __restrict__ gate_w) {
    const int w = threadIdx.x >> 5;
    const int lane = threadIdx.x & 31;
    const int tok0 = blockIdx.x * 16;

    float4 wreg[8];
    const float4* gw = (const float4*)(gate_w + (size_t)w * HDIM);
#pragma unroll
    for (int i = 0; i < 8; i++) wreg[i] = gw[lane + i * 32];

    __shared__ float lg[16][NEXP + 1];
    for (int t = 0; t < 16; t++) {
        const float4* x = (const float4*)(tokens + (size_t)(tok0 + t) * HDIM);
        float s = 0.f;
#pragma unroll
        for (int i = 0; i < 8; i++) {
            float4 a = x[lane + i * 32];
            s += a.x * wreg[i].x + a.y * wreg[i].y + a.z * wreg[i].z + a.w * wreg[i].w;
        }
#pragma unroll
        for (int o = 16; o; o >>= 1) s += __shfl_xor_sync(0xffffffffu, s, o);
        if (lane == 0) lg[t][w] = s;
    }
    __syncthreads();

    if (threadIdx.x < 16) {
        const int t = threadIdx.x;
        const int n = tok0 + t;
        float mx = lg[t][0];
#pragma unroll
        for (int e = 1; e < NEXP; e++) mx = fmaxf(mx, lg[t][e]);
        float p[NEXP], sum = 0.f;
#pragma unroll
        for (int e = 0; e < NEXP; e++) { p[e] = expf(lg[t][e] - mx); sum += p[e]; }
        float b1 = -1.f, b2 = -1.f; int i1 = 0, i2 = 0;
#pragma unroll
        for (int e = 0; e < NEXP; e++) {
            float v = p[e];
            if (v > b1)      { b2 = b1; i2 = i1; b1 = v; i1 = e; }
            else if (v > b2) { b2 = v;  i2 = e; }
        }
        float inv = 1.f / sum;
        g_top2_idx[n * 2 + 0] = i1;
        g_top2_idx[n * 2 + 1] = i2;
        g_top2_w[n * 2 + 0] = b1 * inv;
        g_top2_w[n * 2 + 1] = b2 * inv;
    }
}

// ---------- count + scan ----------
__global__ void __launch_bounds__(512)
count_scan_kernel() {
    __shared__ int hist[16][NEXP];
    const int tid = threadIdx.x, wid = tid >> 5;
    if (tid < 16 * NEXP) ((int*)hist)[tid] = 0;
    __syncthreads();
    for (int i = tid; i < 2 * N_TOK; i += 512)
        atomicAdd(&hist[wid][g_top2_idx[i]], 1);
    __syncthreads();
    if (tid < NEXP) {
        int c = 0;
#pragma unroll
        for (int r = 0; r < 16; r++) c += hist[r][tid];
        g_counts[tid] = c;
        g_fill[tid] = 0;
    }
    __syncthreads();
    if (tid == 0) {
        int acc = 0, accm = 0;
#pragma unroll
        for (int e = 0; e < NEXP; e++) {
            g_offsets[e] = acc; acc += g_counts[e];
            g_mtp[e] = accm;    accm += (g_counts[e] + TM - 1) / TM;
        }
        g_mtp[NEXP] = accm;
        g_units_total = accm * NT;
        g_unit_ctr = 0;
    }
}

// ---------- scatter: warp-aggregated atomics ----------
__global__ void scatter_kernel() {
    const int i = blockIdx.x * 256 + threadIdx.x;
    const int lane = threadIdx.x & 31;
    const int e = g_top2_idx[i];
    unsigned mask = __match_any_sync(0xffffffffu, e);
    int leader = __ffs(mask) - 1;
    int lrank = __popc(mask & ((1u << lane) - 1));
    int base = 0;
    if (lane == leader) base = atomicAdd(&g_fill[e], __popc(mask));
    base = __shfl_sync(0xffffffffu, base, leader);
    int o = g_offsets[e] + base + lrank;
    g_tok[o] = i >> 1;
    g_slot[i] = o;
}

// ---------- persistent tf32 grouped GEMM: 512 thr, 16 warps, 3-stage ----------
__device__ __forceinline__ void cpa16(uint32_t dst, const float* src) {
    asm volatile("cp.async.cg.shared.global [%0], [%1], 16;\n" :: "r"(dst), "l"(src));
}

__global__ void __launch_bounds__(512, 1)
moe_gemm_kernel(const float* __restrict__ tokens,
                const float* __restrict__ expert_w,
                const float* __restrict__ expert_b) {
    extern __shared__ float smem[];
    __shared__ int uinfo[6];
    const uint32_t sbase = (uint32_t)__cvta_generic_to_shared(smem);

    const int tid  = threadIdx.x;
    const int lane = tid & 31;
    const int warp = tid >> 5;
    const int g    = lane >> 2;
    const int c    = lane & 3;
    const int wm0  = (warp & 3) * 32;        // 4 m-groups
    const int wn0  = (warp >> 2) * 64;       // 4 n-groups -> N=256

    for (;;) {
        if (tid == 0) {
            int u = atomicAdd(&g_unit_ctr, 1);
            uinfo[0] = u;
            if (u < g_units_total) {
                int nt = u & (NT - 1);
                int mu = u >> 2;
                int e = 0;
                while (mu >= g_mtp[e + 1]) e++;
                uinfo[1] = e;
                uinfo[2] = (mu - g_mtp[e]) * TM;
                uinfo[3] = nt * TN;
                uinfo[4] = g_offsets[e];
                uinfo[5] = g_counts[e];
            }
        }
        __syncthreads();
        if (uinfo[0] >= g_units_total) break;
        const int e = uinfo[1], m0 = uinfo[2], n0 = uinfo[3];
        const int base = uinfo[4], cnt = uinfo[5];

        // per-thread copy sources: 2 A chunks (j=0,1), 4 B chunks (j=2..5)
        const float* aP[2];
        const float* bP[4];
        uint32_t offA[2], offB[4];
#pragma unroll
        for (int j = 0; j < 2; j++) {
            int slot = tid + j * 512;          // 0..1023
            int r = slot >> 3, c4 = slot & 7;
            offA[j] = (uint32_t)(r * 144 + c4 * 16);
            int m = m0 + r; if (m > cnt - 1) m = cnt - 1;
            aP[j] = tokens + (size_t)g_tok[base + m] * HDIM + c4 * 4;
        }
#pragma unroll
        for (int j = 0; j < 4; j++) {
            int slot = tid + j * 512;          // B rows 0..255
            int r = slot >> 3, c4 = slot & 7;
            offB[j] = (uint32_t)(A_FLOATS * 4 + r * 144 + c4 * 16);
            bP[j] = expert_w + (size_t)e * HDIM * HDIM + (size_t)(n0 + r) * HDIM + c4 * 4;
        }

        auto issue_copy = [&](int kt) {
            uint32_t sb = sbase + (uint32_t)(kt % NSTAGE) * STAGE_BYTES;
            int ko = kt * TK;
#pragma unroll
            for (int j = 0; j < 2; j++) cpa16(sb + offA[j], aP[j] + ko);
#pragma unroll
            for (int j = 0; j < 4; j++) cpa16(sb + offB[j], bP[j + 2 - 2] + ko);
            asm volatile("cp.async.commit_group;\n" ::: "memory");
        };

        float acc[2][8][4];
#pragma unroll
        for (int mi = 0; mi < 2; mi++)
#pragma unroll
            for (int ni = 0; ni < 8; ni++)
#pragma unroll
                for (int r = 0; r < 4; r++) acc[mi][ni][r] = 0.f;

        issue_copy(0);
        issue_copy(1);

        for (int kt = 0; kt < KTILES; kt++) {
            if (kt < KTILES - 1)
                asm volatile("cp.async.wait_group 1;\n" ::: "memory");
            else
                asm volatile("cp.async.wait_group 0;\n" ::: "memory");
            __syncthreads();
            if (kt + 2 < KTILES) issue_copy(kt + 2);

            const float* sA = smem + (kt % NSTAGE) * STAGE_FLOATS;
            const float* sB = sA + A_FLOATS;

#pragma unroll
            for (int ks = 0; ks < 4; ks++) {
                const int k0 = ks * 8;
                uint32_t a0[2], a1[2], a2[2], a3[2];
#pragma unroll
                for (int mi = 0; mi < 2; mi++) {
                    const float* ap = sA + (wm0 + mi * 16 + g) * SLD + k0 + c;
                    a0[mi] = __float_as_uint(ap[0]);
                    a1[mi] = __float_as_uint(ap[8 * SLD]);
                    a2[mi] = __float_as_uint(ap[4]);
                    a3[mi] = __float_as_uint(ap[8 * SLD + 4]);
                }
#pragma unroll
                for (int ni = 0; ni < 8; ni++) {
                    const float* bp = sB + (wn0 + ni * 8 + g) * SLD + k0 + c;
                    uint32_t b0 = __float_as_uint(bp[0]);
                    uint32_t b1 = __float_as_uint(bp[4]);
#pragma unroll
                    for (int mi = 0; mi < 2; mi++) {
                        float* d = acc[mi][ni];
                        asm volatile(
                            "mma.sync.aligned.m16n8k8.row.col.f32.tf32.tf32.f32 "
                            "{%0,%1,%2,%3},{%4,%5,%6,%7},{%8,%9},{%0,%1,%2,%3};\n"
                            : "+f"(d[0]), "+f"(d[1]), "+f"(d[2]), "+f"(d[3])
                            : "r"(a0[mi]), "r"(a1[mi]), "r"(a2[mi]), "r"(a3[mi]),
                              "r"(b0), "r"(b1));
                    }
                }
            }
        }

        // epilogue: relu(acc + bias) -> staging
        float2 bias2[8];
#pragma unroll
        for (int ni = 0; ni < 8; ni++) {
            int n = n0 + wn0 + ni * 8 + 2 * c;
            bias2[ni] = *(const float2*)(expert_b + (size_t)e * HDIM + n);
        }
#pragma unroll
        for (int mi = 0; mi < 2; mi++) {
#pragma unroll
            for (int half = 0; half < 2; half++) {
                int m = m0 + wm0 + mi * 16 + g + half * 8;
                if (m < cnt) {
                    float* orow = g_staging + (size_t)(base + m) * HDIM + n0 + wn0 + 2 * c;
#pragma unroll
                    for (int ni = 0; ni < 8; ni++) {
                        float v0 = fmaxf(acc[mi][ni][half * 2 + 0] + bias2[ni].x, 0.f);
                        float v1 = fmaxf(acc[mi][ni][half * 2 + 1] + bias2[ni].y, 0.f);
                        *(float2*)(orow + ni * 8) = make_float2(v0, v1);
                    }
                }
            }
        }
    }
}

// ---------- combine ----------
__global__ void combine_kernel(float* __restrict__ out) {
    const int n = blockIdx.x;
    const int s0 = g_slot[n * 2], s1 = g_slot[n * 2 + 1];
    const float w0 = g_top2_w[n * 2], w1 = g_top2_w[n * 2 + 1];
    const float4* a = (const float4*)(g_staging + (size_t)s0 * HDIM);
    const float4* b = (const float4*)(g_staging + (size_t)s1 * HDIM);
    float4* o = (float4*)(out + (size_t)n * HDIM);
    for (int i = threadIdx.x; i < HDIM / 4; i += blockDim.x) {
        float4 x = a[i], y = b[i];
        o[i] = make_float4(w0 * x.x + w1 * y.x, w0 * x.y + w1 * y.y,
                           w0 * x.z + w1 * y.z, w0 * x.w + w1 * y.w);
    }
}

extern "C" void kernel_launch(void* const* d_in, const int* in_sizes, int n_in,
                              void* d_out, int out_size) {
    const float* tokens   = (const float*)d_in[0];
    const float* gate_w   = (const float*)d_in[1];
    const float* expert_w = (const float*)d_in[2];
    const float* expert_b = (const float*)d_in[3];
    float* out = (float*)d_out;

    cudaFuncSetAttribute(moe_gemm_kernel,
                         cudaFuncAttributeMaxDynamicSharedMemorySize, SMEM_TOTAL);

    gate_kernel<<<N_TOK / 16, 512>>>(tokens, gate_w);
    count_scan_kernel<<<1, 512>>>();
    scatter_kernel<<<2 * N_TOK / 256, 256>>>();
    moe_gemm_kernel<<<148, 512, SMEM_TOTAL>>>(tokens, expert_w, expert_b);
    combine_kernel<<<N_TOK, 256>>>(out);
}

// round 9
// speedup vs baseline: 1.2965x; 1.1686x over previous
#include <cuda_runtime.h>
#include <cuda_fp16.h>
#include <cstdint>

#define N_TOK 4096
#define HDIM  1024
#define NEXP  16
#define TM 128
#define TN 256
#define TK 32                  // k-halves per tile
#define NT 4                   // HDIM / TN
#define KTILES (HDIM / TK)     // 32
#define SLDH 40                // smem row stride in halves (80B, conflict-free)
#define A_HALVES (TM * SLDH)           // 5120
#define A_BYTES  (A_HALVES * 2)        // 10240
#define STAGE_HALVES ((TM + TN) * SLDH)  // 15360
#define STAGE_BYTES  (STAGE_HALVES * 2)  // 30720
#define NSTAGE 4
#define SMEM_TOTAL (NSTAGE * STAGE_BYTES)  // 122880

__device__ int    g_top2_idx[N_TOK * 2];
__device__ float  g_top2_w[N_TOK * 2];
__device__ int    g_slot[N_TOK * 2];
__device__ int    g_counts[NEXP];
__device__ int    g_offsets[NEXP];
__device__ int    g_fill[NEXP];
__device__ int    g_mtp[NEXP + 1];
__device__ int    g_units_total;
__device__ int    g_unit_ctr;
__device__ int    g_tok[2 * N_TOK];
__device__ float  g_staging[(size_t)2 * N_TOK * HDIM];   // 32 MB
__device__ __half g_wh[(size_t)NEXP * HDIM * HDIM];      // 33.5 MB fp16 expert_w
__device__ __half g_tokh[(size_t)N_TOK * HDIM];          // 8.4 MB fp16 tokens

// ---------- fp32 -> fp16 pre-convert (expert_w + tokens) ----------
__global__ void __launch_bounds__(512)
convert_kernel(const float* __restrict__ w, const float* __restrict__ tok) {
    const size_t stride = (size_t)gridDim.x * 512;
    size_t i = (size_t)blockIdx.x * 512 + threadIdx.x;
    const size_t nw = (size_t)NEXP * HDIM * HDIM / 4;
    const float4* w4 = (const float4*)w;
    for (size_t j = i; j < nw; j += stride) {
        float4 v = w4[j];
        __half2 h0 = __floats2half2_rn(v.x, v.y);
        __half2 h1 = __floats2half2_rn(v.z, v.w);
        *(uint2*)(g_wh + j * 4) = make_uint2(*(uint32_t*)&h0, *(uint32_t*)&h1);
    }
    const size_t ntk = (size_t)N_TOK * HDIM / 4;
    const float4* t4 = (const float4*)tok;
    for (size_t j = i; j < ntk; j += stride) {
        float4 v = t4[j];
        __half2 h0 = __floats2half2_rn(v.x, v.y);
        __half2 h1 = __floats2half2_rn(v.z, v.w);
        *(uint2*)(g_tokh + j * 4) = make_uint2(*(uint32_t*)&h0, *(uint32_t*)&h1);
    }
}

// ---------- gate (fp32, exact) ----------
__global__ void __launch_bounds__(512)
gate_kernel(const float* __restrict__ tokens, const float* __restrict__ gate_w) {
    const int w = threadIdx.x >> 5;
    const int lane = threadIdx.x & 31;
    const int tok0 = blockIdx.x * 16;

    float4 wreg[8];
    const float4* gw = (const float4*)(gate_w + (size_t)w * HDIM);
#pragma unroll
    for (int i = 0; i < 8; i++) wreg[i] = gw[lane + i * 32];

    __shared__ float lg[16][NEXP + 1];
    for (int t = 0; t < 16; t++) {
        const float4* x = (const float4*)(tokens + (size_t)(tok0 + t) * HDIM);
        float s = 0.f;
#pragma unroll
        for (int i = 0; i < 8; i++) {
            float4 a = x[lane + i * 32];
            s += a.x * wreg[i].x + a.y * wreg[i].y + a.z * wreg[i].z + a.w * wreg[i].w;
        }
#pragma unroll
        for (int o = 16; o; o >>= 1) s += __shfl_xor_sync(0xffffffffu, s, o);
        if (lane == 0) lg[t][w] = s;
    }
    __syncthreads();

    if (threadIdx.x < 16) {
        const int t = threadIdx.x;
        const int n = tok0 + t;
        float mx = lg[t][0];
#pragma unroll
        for (int e = 1; e < NEXP; e++) mx = fmaxf(mx, lg[t][e]);
        float p[NEXP], sum = 0.f;
#pragma unroll
        for (int e = 0; e < NEXP; e++) { p[e] = expf(lg[t][e] - mx); sum += p[e]; }
        float b1 = -1.f, b2 = -1.f; int i1 = 0, i2 = 0;
#pragma unroll
        for (int e = 0; e < NEXP; e++) {
            float v = p[e];
            if (v > b1)      { b2 = b1; i2 = i1; b1 = v; i1 = e; }
            else if (v > b2) { b2 = v;  i2 = e; }
        }
        float inv = 1.f / sum;
        g_top2_idx[n * 2 + 0] = i1;
        g_top2_idx[n * 2 + 1] = i2;
        g_top2_w[n * 2 + 0] = b1 * inv;
        g_top2_w[n * 2 + 1] = b2 * inv;
    }
}

// ---------- count + scan ----------
__global__ void __launch_bounds__(512)
count_scan_kernel() {
    __shared__ int hist[16][NEXP];
    const int tid = threadIdx.x, wid = tid >> 5;
    if (tid < 16 * NEXP) ((int*)hist)[tid] = 0;
    __syncthreads();
    for (int i = tid; i < 2 * N_TOK; i += 512)
        atomicAdd(&hist[wid][g_top2_idx[i]], 1);
    __syncthreads();
    if (tid < NEXP) {
        int c = 0;
#pragma unroll
        for (int r = 0; r < 16; r++) c += hist[r][tid];
        g_counts[tid] = c;
        g_fill[tid] = 0;
    }
    __syncthreads();
    if (tid == 0) {
        int acc = 0, accm = 0;
#pragma unroll
        for (int e = 0; e < NEXP; e++) {
            g_offsets[e] = acc; acc += g_counts[e];
            g_mtp[e] = accm;    accm += (g_counts[e] + TM - 1) / TM;
        }
        g_mtp[NEXP] = accm;
        g_units_total = accm * NT;
        g_unit_ctr = 0;
    }
}

// ---------- scatter ----------
__global__ void scatter_kernel() {
    const int i = blockIdx.x * 256 + threadIdx.x;
    const int lane = threadIdx.x & 31;
    const int e = g_top2_idx[i];
    unsigned mask = __match_any_sync(0xffffffffu, e);
    int leader = __ffs(mask) - 1;
    int lrank = __popc(mask & ((1u << lane) - 1));
    int base = 0;
    if (lane == leader) base = atomicAdd(&g_fill[e], __popc(mask));
    base = __shfl_sync(0xffffffffu, base, leader);
    int o = g_offsets[e] + base + lrank;
    g_tok[o] = i >> 1;
    g_slot[i] = o;
}

// ---------- persistent fp16 grouped GEMM: 512 thr, 4-stage cp.async ----------
__device__ __forceinline__ void cpa16(uint32_t dst, const __half* src) {
    asm volatile("cp.async.cg.shared.global [%0], [%1], 16;\n" :: "r"(dst), "l"(src));
}

__global__ void __launch_bounds__(512, 1)
moe_gemm_kernel(const float* __restrict__ expert_b) {
    extern __shared__ __half smemh[];
    __shared__ int uinfo[6];
    const uint32_t sbase = (uint32_t)__cvta_generic_to_shared(smemh);

    const int tid  = threadIdx.x;
    const int lane = tid & 31;
    const int warp = tid >> 5;
    const int g    = lane >> 2;
    const int c    = lane & 3;
    const int wm0  = (warp & 3) * 32;
    const int wn0  = (warp >> 2) * 64;

    for (;;) {
        if (tid == 0) {
            int u = atomicAdd(&g_unit_ctr, 1);
            uinfo[0] = u;
            if (u < g_units_total) {
                int nt = u & (NT - 1);
                int mu = u >> 2;
                int e = 0;
                while (mu >= g_mtp[e + 1]) e++;
                uinfo[1] = e;
                uinfo[2] = (mu - g_mtp[e]) * TM;
                uinfo[3] = nt * TN;
                uinfo[4] = g_offsets[e];
                uinfo[5] = g_counts[e];
            }
        }
        __syncthreads();
        if (uinfo[0] >= g_units_total) break;
        const int e = uinfo[1], m0 = uinfo[2], n0 = uinfo[3];
        const int base = uinfo[4], cnt = uinfo[5];

        // copy sources: 1 A chunk + 2 B chunks per thread (16B each)
        const __half* aP;
        const __half* bP[2];
        uint32_t offA, offB[2];
        {
            int r = tid >> 2, c4 = tid & 3;
            offA = (uint32_t)(r * 80 + c4 * 16);
            int m = m0 + r; if (m > cnt - 1) m = cnt - 1;
            aP = g_tokh + ((size_t)g_tok[base + m] << 10) + c4 * 8;
#pragma unroll
            for (int j = 0; j < 2; j++) {
                int id = tid + j * 512;
                int rb = id >> 2, cb = id & 3;
                offB[j] = (uint32_t)(A_BYTES + rb * 80 + cb * 16);
                bP[j] = g_wh + ((size_t)e << 20) + ((size_t)(n0 + rb) << 10) + cb * 8;
            }
        }

        auto issue_copy = [&](int kt) {
            uint32_t sb = sbase + (uint32_t)(kt & (NSTAGE - 1)) * STAGE_BYTES;
            int ko = kt * TK;
            cpa16(sb + offA, aP + ko);
            cpa16(sb + offB[0], bP[0] + ko);
            cpa16(sb + offB[1], bP[1] + ko);
            asm volatile("cp.async.commit_group;\n" ::: "memory");
        };

        float acc[2][8][4];
#pragma unroll
        for (int mi = 0; mi < 2; mi++)
#pragma unroll
            for (int ni = 0; ni < 8; ni++)
#pragma unroll
                for (int r = 0; r < 4; r++) acc[mi][ni][r] = 0.f;

        issue_copy(0); issue_copy(1); issue_copy(2);

        for (int kt = 0; kt < KTILES; kt++) {
            if (kt <= KTILES - 3)
                asm volatile("cp.async.wait_group 2;\n" ::: "memory");
            else if (kt == KTILES - 2)
                asm volatile("cp.async.wait_group 1;\n" ::: "memory");
            else
                asm volatile("cp.async.wait_group 0;\n" ::: "memory");
            __syncthreads();
            if (kt + 3 < KTILES) issue_copy(kt + 3);

            const __half* sA = smemh + (kt & (NSTAGE - 1)) * STAGE_HALVES;
            const __half* sB = sA + A_HALVES;

#pragma unroll
            for (int ks = 0; ks < 2; ks++) {
                const int k0 = ks * 16;
                uint32_t a0[2], a1[2], a2[2], a3[2];
#pragma unroll
                for (int mi = 0; mi < 2; mi++) {
                    const __half* ap = sA + (wm0 + mi * 16 + g) * SLDH + k0 + 2 * c;
                    a0[mi] = *(const uint32_t*)ap;
                    a1[mi] = *(const uint32_t*)(ap + 8 * SLDH);
                    a2[mi] = *(const uint32_t*)(ap + 8);
                    a3[mi] = *(const uint32_t*)(ap + 8 * SLDH + 8);
                }
#pragma unroll
                for (int ni = 0; ni < 8; ni++) {
                    const __half* bp = sB + (wn0 + ni * 8 + g) * SLDH + k0 + 2 * c;
                    uint32_t b0 = *(const uint32_t*)bp;
                    uint32_t b1 = *(const uint32_t*)(bp + 8);
#pragma unroll
                    for (int mi = 0; mi < 2; mi++) {
                        float* d = acc[mi][ni];
                        asm volatile(
                            "mma.sync.aligned.m16n8k16.row.col.f32.f16.f16.f32 "
                            "{%0,%1,%2,%3},{%4,%5,%6,%7},{%8,%9},{%0,%1,%2,%3};\n"
                            : "+f"(d[0]), "+f"(d[1]), "+f"(d[2]), "+f"(d[3])
                            : "r"(a0[mi]), "r"(a1[mi]), "r"(a2[mi]), "r"(a3[mi]),
                              "r"(b0), "r"(b1));
                    }
                }
            }
        }

        // epilogue: relu(acc + bias) -> staging (fp32)
        float2 bias2[8];
#pragma unroll
        for (int ni = 0; ni < 8; ni++) {
            int n = n0 + wn0 + ni * 8 + 2 * c;
            bias2[ni] = *(const float2*)(expert_b + (size_t)e * HDIM + n);
        }
#pragma unroll
        for (int mi = 0; mi < 2; mi++) {
#pragma unroll
            for (int half = 0; half < 2; half++) {
                int m = m0 + wm0 + mi * 16 + g + half * 8;
                if (m < cnt) {
                    float* orow = g_staging + (size_t)(base + m) * HDIM + n0 + wn0 + 2 * c;
#pragma unroll
                    for (int ni = 0; ni < 8; ni++) {
                        float v0 = fmaxf(acc[mi][ni][half * 2 + 0] + bias2[ni].x, 0.f);
                        float v1 = fmaxf(acc[mi][ni][half * 2 + 1] + bias2[ni].y, 0.f);
                        *(float2*)(orow + ni * 8) = make_float2(v0, v1);
                    }
                }
            }
        }
    }
}

// ---------- combine ----------
__global__ void combine_kernel(float* __restrict__ out) {
    const int n = blockIdx.x;
    const int s0 = g_slot[n * 2], s1 = g_slot[n * 2 + 1];
    const float w0 = g_top2_w[n * 2], w1 = g_top2_w[n * 2 + 1];
    const float4* a = (const float4*)(g_staging + (size_t)s0 * HDIM);
    const float4* b = (const float4*)(g_staging + (size_t)s1 * HDIM);
    float4* o = (float4*)(out + (size_t)n * HDIM);
    for (int i = threadIdx.x; i < HDIM / 4; i += blockDim.x) {
        float4 x = a[i], y = b[i];
        o[i] = make_float4(w0 * x.x + w1 * y.x, w0 * x.y + w1 * y.y,
                           w0 * x.z + w1 * y.z, w0 * x.w + w1 * y.w);
    }
}

extern "C" void kernel_launch(void* const* d_in, const int* in_sizes, int n_in,
                              void* d_out, int out_size) {
    const float* tokens   = (const float*)d_in[0];
    const float* gate_w   = (const float*)d_in[1];
    const float* expert_w = (const float*)d_in[2];
    const float* expert_b = (const float*)d_in[3];
    float* out = (float*)d_out;

    cudaFuncSetAttribute(moe_gemm_kernel,
                         cudaFuncAttributeMaxDynamicSharedMemorySize, SMEM_TOTAL);

    convert_kernel<<<1184, 512>>>(expert_w, tokens);
    gate_kernel<<<N_TOK / 16, 512>>>(tokens, gate_w);
    count_scan_kernel<<<1, 512>>>();
    scatter_kernel<<<2 * N_TOK / 256, 256>>>();
    moe_gemm_kernel<<<148, 512, SMEM_TOTAL>>>(expert_b);
    combine_kernel<<<N_TOK, 256>>>(out);
}

// round 10
// speedup vs baseline: 1.4397x; 1.1105x over previous
#include <cuda_runtime.h>
#include <cuda_fp16.h>
#include <cstdint>

#define N_TOK 4096
#define HDIM  1024
#define NEXP  16
#define TM 128
#define TN 256
#define TK 32                  // halves per k-tile
#define NT 4
#define KTILES (HDIM / TK)     // 32
#define SLDH 40                // 80B row stride: conflict-free for ldmatrix
#define A_HALVES (TM * SLDH)
#define A_BYTES  (A_HALVES * 2)
#define STAGE_HALVES ((TM + TN) * SLDH)
#define STAGE_BYTES  (STAGE_HALVES * 2)
#define NSTAGE 4
#define SMEM_TOTAL (NSTAGE * STAGE_BYTES)   // 122880

#define NGATE 256              // gate blocks (16 tokens each)
#define NCONV 928              // expert_w convert blocks

__device__ int    g_top2_idx[N_TOK * 2];
__device__ float  g_top2_w[N_TOK * 2];
__device__ int    g_slot[N_TOK * 2];
__device__ int    g_counts[NEXP];
__device__ int    g_offsets[NEXP];
__device__ int    g_mtp[NEXP + 1];
__device__ int    g_units_total;
__device__ int    g_unit_ctr;
__device__ int    g_tok[2 * N_TOK];
__device__ float  g_staging[(size_t)2 * N_TOK * HDIM];
__device__ __half g_wh[(size_t)NEXP * HDIM * HDIM];
__device__ __half g_tokh[(size_t)N_TOK * HDIM];

// ---------- prep: gate (+ fp16 token write) fused with expert_w convert ----------
__global__ void __launch_bounds__(512)
prep_kernel(const float* __restrict__ tokens, const float* __restrict__ gate_w,
            const float* __restrict__ expert_w) {
    if (blockIdx.x >= NGATE) {
        // ---- expert_w fp32 -> fp16 ----
        const size_t stride = (size_t)NCONV * 512;
        size_t i = (size_t)(blockIdx.x - NGATE) * 512 + threadIdx.x;
        const size_t nw = (size_t)NEXP * HDIM * HDIM / 4;
        const float4* w4 = (const float4*)expert_w;
        for (size_t j = i; j < nw; j += stride) {
            float4 v = w4[j];
            __half2 h0 = __floats2half2_rn(v.x, v.y);
            __half2 h1 = __floats2half2_rn(v.z, v.w);
            *(uint2*)(g_wh + j * 4) = make_uint2(*(uint32_t*)&h0, *(uint32_t*)&h1);
        }
        return;
    }
    // ---- gate: 16 tokens, warp e holds gate_w[e] in regs ----
    const int w = threadIdx.x >> 5;
    const int lane = threadIdx.x & 31;
    const int tok0 = blockIdx.x * 16;

    float4 wreg[8];
    const float4* gw = (const float4*)(gate_w + (size_t)w * HDIM);
#pragma unroll
    for (int i = 0; i < 8; i++) wreg[i] = gw[lane + i * 32];

    __shared__ float lg[16][NEXP + 1];
    for (int t = 0; t < 16; t++) {
        const float4* x = (const float4*)(tokens + (size_t)(tok0 + t) * HDIM);
        float s = 0.f;
#pragma unroll
        for (int i = 0; i < 8; i++) {
            float4 a = x[lane + i * 32];
            s += a.x * wreg[i].x + a.y * wreg[i].y + a.z * wreg[i].z + a.w * wreg[i].w;
        }
#pragma unroll
        for (int o = 16; o; o >>= 1) s += __shfl_xor_sync(0xffffffffu, s, o);
        if (lane == 0) lg[t][w] = s;
    }

    // fp16 token conversion for these 16 tokens (L2 hits)
    {
        const float4* t4 = (const float4*)(tokens + (size_t)tok0 * HDIM);
        __half* th = g_tokh + (size_t)tok0 * HDIM;
#pragma unroll
        for (int j = 0; j < 8; j++) {
            int idx = threadIdx.x + j * 512;          // 4096 float4
            float4 v = t4[idx];
            __half2 h0 = __floats2half2_rn(v.x, v.y);
            __half2 h1 = __floats2half2_rn(v.z, v.w);
            *(uint2*)(th + idx * 4) = make_uint2(*(uint32_t*)&h0, *(uint32_t*)&h1);
        }
    }
    __syncthreads();

    if (threadIdx.x < 16) {
        const int t = threadIdx.x;
        const int n = tok0 + t;
        float mx = lg[t][0];
#pragma unroll
        for (int e = 1; e < NEXP; e++) mx = fmaxf(mx, lg[t][e]);
        float p[NEXP], sum = 0.f;
#pragma unroll
        for (int e = 0; e < NEXP; e++) { p[e] = expf(lg[t][e] - mx); sum += p[e]; }
        float b1 = -1.f, b2 = -1.f; int i1 = 0, i2 = 0;
#pragma unroll
        for (int e = 0; e < NEXP; e++) {
            float v = p[e];
            if (v > b1)      { b2 = b1; i2 = i1; b1 = v; i1 = e; }
            else if (v > b2) { b2 = v;  i2 = e; }
        }
        float inv = 1.f / sum;
        g_top2_idx[n * 2 + 0] = i1;
        g_top2_idx[n * 2 + 1] = i2;
        g_top2_w[n * 2 + 0] = b1 * inv;
        g_top2_w[n * 2 + 1] = b2 * inv;
    }
}

// ---------- route: count + scan + scatter in one block ----------
__global__ void __launch_bounds__(512)
route_kernel() {
    __shared__ int hist[16][NEXP];
    __shared__ int s_fill[NEXP];
    const int tid = threadIdx.x, wid = tid >> 5, lane = tid & 31;
    if (tid < 16 * NEXP) ((int*)hist)[tid] = 0;
    if (tid < NEXP) s_fill[tid] = 0;
    __syncthreads();
    for (int i = tid; i < 2 * N_TOK; i += 512)
        atomicAdd(&hist[wid][g_top2_idx[i]], 1);
    __syncthreads();
    if (tid < NEXP) {
        int c = 0;
#pragma unroll
        for (int r = 0; r < 16; r++) c += hist[r][tid];
        g_counts[tid] = c;
    }
    __syncthreads();
    if (tid == 0) {
        int acc = 0, accm = 0;
#pragma unroll
        for (int e = 0; e < NEXP; e++) {
            g_offsets[e] = acc; acc += g_counts[e];
            g_mtp[e] = accm;    accm += (g_counts[e] + TM - 1) / TM;
        }
        g_mtp[NEXP] = accm;
        g_units_total = accm * NT;
        g_unit_ctr = 0;
    }
    __syncthreads();
    // scatter with warp-aggregated shared atomics
    for (int i = tid; i < 2 * N_TOK; i += 512) {
        const int e = g_top2_idx[i];
        unsigned mask = __match_any_sync(0xffffffffu, e);
        int leader = __ffs(mask) - 1;
        int lrank = __popc(mask & ((1u << lane) - 1));
        int base = 0;
        if (lane == leader) base = atomicAdd(&s_fill[e], __popc(mask));
        base = __shfl_sync(0xffffffffu, base, leader);
        int o = g_offsets[e] + base + lrank;
        g_tok[o] = i >> 1;
        g_slot[i] = o;
    }
}

// ---------- persistent fp16 grouped GEMM: ldmatrix fragments ----------
__device__ __forceinline__ void cpa16(uint32_t dst, const __half* src) {
    asm volatile("cp.async.cg.shared.global [%0], [%1], 16;\n" :: "r"(dst), "l"(src));
}
__device__ __forceinline__ void ldsm4(uint32_t& r0, uint32_t& r1, uint32_t& r2,
                                      uint32_t& r3, uint32_t a) {
    asm volatile("ldmatrix.sync.aligned.m8n8.x4.shared.b16 {%0,%1,%2,%3}, [%4];"
                 : "=r"(r0), "=r"(r1), "=r"(r2), "=r"(r3) : "r"(a));
}

__global__ void __launch_bounds__(512, 1)
moe_gemm_kernel(const float* __restrict__ expert_b) {
    extern __shared__ __half smemh[];
    __shared__ int uinfo[6];
    const uint32_t sbase = (uint32_t)__cvta_generic_to_shared(smemh);

    const int tid  = threadIdx.x;
    const int lane = tid & 31;
    const int warp = tid >> 5;
    const int g    = lane >> 2;
    const int c    = lane & 3;
    const int wm0  = (warp & 3) * 32;
    const int wn0  = (warp >> 2) * 64;

    // ldmatrix lane addressing: group = lane>>3, row_in = lane&7
    const int grp = lane >> 3, rin = lane & 7;
    uint32_t aoff[2], boff[4];
#pragma unroll
    for (int mi = 0; mi < 2; mi++)
        aoff[mi] = (uint32_t)(((wm0 + mi * 16 + (grp & 1) * 8 + rin) * SLDH
                               + (grp >> 1) * 8) * 2);
#pragma unroll
    for (int p = 0; p < 4; p++)
        boff[p] = (uint32_t)(A_BYTES + ((wn0 + p * 16 + (grp >> 1) * 8 + rin) * SLDH
                                        + (grp & 1) * 8) * 2);

    for (;;) {
        if (tid == 0) {
            int u = atomicAdd(&g_unit_ctr, 1);
            uinfo[0] = u;
            if (u < g_units_total) {
                int nt = u & (NT - 1);
                int mu = u >> 2;
                int e = 0;
                while (mu >= g_mtp[e + 1]) e++;
                uinfo[1] = e;
                uinfo[2] = (mu - g_mtp[e]) * TM;
                uinfo[3] = nt * TN;
                uinfo[4] = g_offsets[e];
                uinfo[5] = g_counts[e];
            }
        }
        __syncthreads();
        if (uinfo[0] >= g_units_total) break;
        const int e = uinfo[1], m0 = uinfo[2], n0 = uinfo[3];
        const int base = uinfo[4], cnt = uinfo[5];

        const __half* aP;
        const __half* bP[2];
        uint32_t offA, offB[2];
        {
            int r = tid >> 2, c4 = tid & 3;
            offA = (uint32_t)(r * 80 + c4 * 16);
            int m = m0 + r; if (m > cnt - 1) m = cnt - 1;
            aP = g_tokh + ((size_t)g_tok[base + m] << 10) + c4 * 8;
#pragma unroll
            for (int j = 0; j < 2; j++) {
                int id = tid + j * 512;
                int rb = id >> 2, cb = id & 3;
                offB[j] = (uint32_t)(A_BYTES + rb * 80 + cb * 16);
                bP[j] = g_wh + ((size_t)e << 20) + ((size_t)(n0 + rb) << 10) + cb * 8;
            }
        }

        auto issue_copy = [&](int kt) {
            uint32_t sb = sbase + (uint32_t)(kt & (NSTAGE - 1)) * STAGE_BYTES;
            int ko = kt * TK;
            cpa16(sb + offA, aP + ko);
            cpa16(sb + offB[0], bP[0] + ko);
            cpa16(sb + offB[1], bP[1] + ko);
            asm volatile("cp.async.commit_group;\n" ::: "memory");
        };

        float acc[2][8][4];
#pragma unroll
        for (int mi = 0; mi < 2; mi++)
#pragma unroll
            for (int ni = 0; ni < 8; ni++)
#pragma unroll
                for (int r = 0; r < 4; r++) acc[mi][ni][r] = 0.f;

        issue_copy(0); issue_copy(1); issue_copy(2);

        for (int kt = 0; kt < KTILES; kt++) {
            if (kt <= KTILES - 3)
                asm volatile("cp.async.wait_group 2;\n" ::: "memory");
            else if (kt == KTILES - 2)
                asm volatile("cp.async.wait_group 1;\n" ::: "memory");
            else
                asm volatile("cp.async.wait_group 0;\n" ::: "memory");
            __syncthreads();
            if (kt + 3 < KTILES) issue_copy(kt + 3);

            const uint32_t stg = sbase + (uint32_t)(kt & (NSTAGE - 1)) * STAGE_BYTES;

#pragma unroll
            for (int ks = 0; ks < 2; ks++) {
                const uint32_t kb = (uint32_t)(ks * 32);   // 16 halves
                uint32_t a[2][4];
#pragma unroll
                for (int mi = 0; mi < 2; mi++)
                    ldsm4(a[mi][0], a[mi][1], a[mi][2], a[mi][3], stg + aoff[mi] + kb);
#pragma unroll
                for (int p = 0; p < 4; p++) {
                    uint32_t b0, b1, b2, b3;
                    ldsm4(b0, b1, b2, b3, stg + boff[p] + kb);
#pragma unroll
                    for (int mi = 0; mi < 2; mi++) {
                        float* d0 = acc[mi][p * 2];
                        float* d1 = acc[mi][p * 2 + 1];
                        asm volatile(
                            "mma.sync.aligned.m16n8k16.row.col.f32.f16.f16.f32 "
                            "{%0,%1,%2,%3},{%4,%5,%6,%7},{%8,%9},{%0,%1,%2,%3};\n"
                            : "+f"(d0[0]), "+f"(d0[1]), "+f"(d0[2]), "+f"(d0[3])
                            : "r"(a[mi][0]), "r"(a[mi][1]), "r"(a[mi][2]), "r"(a[mi][3]),
                              "r"(b0), "r"(b1));
                        asm volatile(
                            "mma.sync.aligned.m16n8k16.row.col.f32.f16.f16.f32 "
                            "{%0,%1,%2,%3},{%4,%5,%6,%7},{%8,%9},{%0,%1,%2,%3};\n"
                            : "+f"(d1[0]), "+f"(d1[1]), "+f"(d1[2]), "+f"(d1[3])
                            : "r"(a[mi][0]), "r"(a[mi][1]), "r"(a[mi][2]), "r"(a[mi][3]),
                              "r"(b2), "r"(b3));
                    }
                }
            }
        }

        // epilogue
        float2 bias2[8];
#pragma unroll
        for (int ni = 0; ni < 8; ni++) {
            int n = n0 + wn0 + ni * 8 + 2 * c;
            bias2[ni] = *(const float2*)(expert_b + (size_t)e * HDIM + n);
        }
#pragma unroll
        for (int mi = 0; mi < 2; mi++) {
#pragma unroll
            for (int half = 0; half < 2; half++) {
                int m = m0 + wm0 + mi * 16 + g + half * 8;
                if (m < cnt) {
                    float* orow = g_staging + (size_t)(base + m) * HDIM + n0 + wn0 + 2 * c;
#pragma unroll
                    for (int ni = 0; ni < 8; ni++) {
                        float v0 = fmaxf(acc[mi][ni][half * 2 + 0] + bias2[ni].x, 0.f);
                        float v1 = fmaxf(acc[mi][ni][half * 2 + 1] + bias2[ni].y, 0.f);
                        *(float2*)(orow + ni * 8) = make_float2(v0, v1);
                    }
                }
            }
        }
    }
}

// ---------- combine ----------
__global__ void combine_kernel(float* __restrict__ out) {
    const int n = blockIdx.x;
    const int s0 = g_slot[n * 2], s1 = g_slot[n * 2 + 1];
    const float w0 = g_top2_w[n * 2], w1 = g_top2_w[n * 2 + 1];
    const float4* a = (const float4*)(g_staging + (size_t)s0 * HDIM);
    const float4* b = (const float4*)(g_staging + (size_t)s1 * HDIM);
    float4* o = (float4*)(out + (size_t)n * HDIM);
    for (int i = threadIdx.x; i < HDIM / 4; i += blockDim.x) {
        float4 x = a[i], y = b[i];
        o[i] = make_float4(w0 * x.x + w1 * y.x, w0 * x.y + w1 * y.y,
                           w0 * x.z + w1 * y.z, w0 * x.w + w1 * y.w);
    }
}

extern "C" void kernel_launch(void* const* d_in, const int* in_sizes, int n_in,
                              void* d_out, int out_size) {
    const float* tokens   = (const float*)d_in[0];
    const float* gate_w   = (const float*)d_in[1];
    const float* expert_w = (const float*)d_in[2];
    const float* expert_b = (const float*)d_in[3];
    float* out = (float*)d_out;

    cudaFuncSetAttribute(moe_gemm_kernel,
                         cudaFuncAttributeMaxDynamicSharedMemorySize, SMEM_TOTAL);

    prep_kernel<<<NGATE + NCONV, 512>>>(tokens, gate_w, expert_w);
    route_kernel<<<1, 512>>>();
    moe_gemm_kernel<<<148, 512, SMEM_TOTAL>>>(expert_b);
    combine_kernel<<<N_TOK, 256>>>(out);
}

// round 11
// speedup vs baseline: 1.4602x; 1.0143x over previous
#include <cuda_runtime.h>
#include <cuda_fp16.h>
#include <cstdint>

#define N_TOK 4096
#define HDIM  1024
#define NEXP  16
#define TM 128
#define TN 256
#define TK 32                  // halves per k-tile
#define NT 4
#define KTILES (HDIM / TK)     // 32
#define SLDH 40                // 80B row stride: conflict-free for ldmatrix
#define A_HALVES (TM * SLDH)
#define A_BYTES  (A_HALVES * 2)
#define STAGE_HALVES ((TM + TN) * SLDH)
#define STAGE_BYTES  (STAGE_HALVES * 2)    // 30720
#define NSTAGE 6
#define SMEM_TOTAL (NSTAGE * STAGE_BYTES)  // 184320

#define NGATE 256
#define NCONV 928

__device__ int    g_top2_idx[N_TOK * 2];
__device__ float  g_top2_w[N_TOK * 2];
__device__ int    g_slot[N_TOK * 2];
__device__ int    g_counts[NEXP];
__device__ int    g_offsets[NEXP];
__device__ int    g_mtp[NEXP + 1];
__device__ int    g_units_total;
__device__ int    g_unit_ctr;
__device__ int    g_tok[2 * N_TOK];
__device__ __half g_staging[(size_t)2 * N_TOK * HDIM];   // 16 MB fp16 staging
__device__ __half g_wh[(size_t)NEXP * HDIM * HDIM];
__device__ __half g_tokh[(size_t)N_TOK * HDIM];

// ---------- prep: gate (+ fp16 token write) fused with expert_w convert ----------
__global__ void __launch_bounds__(512)
prep_kernel(const float* __restrict__ tokens, const float* __restrict__ gate_w,
            const float* __restrict__ expert_w) {
    if (blockIdx.x >= NGATE) {
        const size_t stride = (size_t)NCONV * 512;
        size_t i = (size_t)(blockIdx.x - NGATE) * 512 + threadIdx.x;
        const size_t nw = (size_t)NEXP * HDIM * HDIM / 4;
        const float4* w4 = (const float4*)expert_w;
        for (size_t j = i; j < nw; j += stride) {
            float4 v = w4[j];
            __half2 h0 = __floats2half2_rn(v.x, v.y);
            __half2 h1 = __floats2half2_rn(v.z, v.w);
            *(uint2*)(g_wh + j * 4) = make_uint2(*(uint32_t*)&h0, *(uint32_t*)&h1);
        }
        return;
    }
    const int w = threadIdx.x >> 5;
    const int lane = threadIdx.x & 31;
    const int tok0 = blockIdx.x * 16;

    float4 wreg[8];
    const float4* gw = (const float4*)(gate_w + (size_t)w * HDIM);
#pragma unroll
    for (int i = 0; i < 8; i++) wreg[i] = gw[lane + i * 32];

    __shared__ float lg[16][NEXP + 1];
    for (int t = 0; t < 16; t++) {
        const float4* x = (const float4*)(tokens + (size_t)(tok0 + t) * HDIM);
        float s = 0.f;
#pragma unroll
        for (int i = 0; i < 8; i++) {
            float4 a = x[lane + i * 32];
            s += a.x * wreg[i].x + a.y * wreg[i].y + a.z * wreg[i].z + a.w * wreg[i].w;
        }
#pragma unroll
        for (int o = 16; o; o >>= 1) s += __shfl_xor_sync(0xffffffffu, s, o);
        if (lane == 0) lg[t][w] = s;
    }
    {
        const float4* t4 = (const float4*)(tokens + (size_t)tok0 * HDIM);
        __half* th = g_tokh + (size_t)tok0 * HDIM;
#pragma unroll
        for (int j = 0; j < 8; j++) {
            int idx = threadIdx.x + j * 512;
            float4 v = t4[idx];
            __half2 h0 = __floats2half2_rn(v.x, v.y);
            __half2 h1 = __floats2half2_rn(v.z, v.w);
            *(uint2*)(th + idx * 4) = make_uint2(*(uint32_t*)&h0, *(uint32_t*)&h1);
        }
    }
    __syncthreads();

    if (threadIdx.x < 16) {
        const int t = threadIdx.x;
        const int n = tok0 + t;
        float mx = lg[t][0];
#pragma unroll
        for (int e = 1; e < NEXP; e++) mx = fmaxf(mx, lg[t][e]);
        float p[NEXP], sum = 0.f;
#pragma unroll
        for (int e = 0; e < NEXP; e++) { p[e] = expf(lg[t][e] - mx); sum += p[e]; }
        float b1 = -1.f, b2 = -1.f; int i1 = 0, i2 = 0;
#pragma unroll
        for (int e = 0; e < NEXP; e++) {
            float v = p[e];
            if (v > b1)      { b2 = b1; i2 = i1; b1 = v; i1 = e; }
            else if (v > b2) { b2 = v;  i2 = e; }
        }
        float inv = 1.f / sum;
        g_top2_idx[n * 2 + 0] = i1;
        g_top2_idx[n * 2 + 1] = i2;
        g_top2_w[n * 2 + 0] = b1 * inv;
        g_top2_w[n * 2 + 1] = b2 * inv;
    }
}

// ---------- route: count + scan + scatter ----------
__global__ void __launch_bounds__(512)
route_kernel() {
    __shared__ int hist[16][NEXP];
    __shared__ int s_fill[NEXP];
    const int tid = threadIdx.x, wid = tid >> 5, lane = tid & 31;
    if (tid < 16 * NEXP) ((int*)hist)[tid] = 0;
    if (tid < NEXP) s_fill[tid] = 0;
    __syncthreads();
    for (int i = tid; i < 2 * N_TOK; i += 512)
        atomicAdd(&hist[wid][g_top2_idx[i]], 1);
    __syncthreads();
    if (tid < NEXP) {
        int c = 0;
#pragma unroll
        for (int r = 0; r < 16; r++) c += hist[r][tid];
        g_counts[tid] = c;
    }
    __syncthreads();
    if (tid == 0) {
        int acc = 0, accm = 0;
#pragma unroll
        for (int e = 0; e < NEXP; e++) {
            g_offsets[e] = acc; acc += g_counts[e];
            g_mtp[e] = accm;    accm += (g_counts[e] + TM - 1) / TM;
        }
        g_mtp[NEXP] = accm;
        g_units_total = accm * NT;
        g_unit_ctr = 0;
    }
    __syncthreads();
    for (int i = tid; i < 2 * N_TOK; i += 512) {
        const int e = g_top2_idx[i];
        unsigned mask = __match_any_sync(0xffffffffu, e);
        int leader = __ffs(mask) - 1;
        int lrank = __popc(mask & ((1u << lane) - 1));
        int base = 0;
        if (lane == leader) base = atomicAdd(&s_fill[e], __popc(mask));
        base = __shfl_sync(0xffffffffu, base, leader);
        int o = g_offsets[e] + base + lrank;
        g_tok[o] = i >> 1;
        g_slot[i] = o;
    }
}

// ---------- persistent fp16 grouped GEMM: 6-stage, 1 barrier / 2 k-tiles ----------
__device__ __forceinline__ void cpa16(uint32_t dst, const __half* src) {
    asm volatile("cp.async.cg.shared.global [%0], [%1], 16;\n" :: "r"(dst), "l"(src));
}
__device__ __forceinline__ void ldsm4(uint32_t& r0, uint32_t& r1, uint32_t& r2,
                                      uint32_t& r3, uint32_t a) {
    asm volatile("ldmatrix.sync.aligned.m8n8.x4.shared.b16 {%0,%1,%2,%3}, [%4];"
                 : "=r"(r0), "=r"(r1), "=r"(r2), "=r"(r3) : "r"(a));
}

__global__ void __launch_bounds__(512, 1)
moe_gemm_kernel(const float* __restrict__ expert_b) {
    extern __shared__ __half smemh[];
    __shared__ int uinfo[6];
    const uint32_t sbase = (uint32_t)__cvta_generic_to_shared(smemh);

    const int tid  = threadIdx.x;
    const int lane = tid & 31;
    const int warp = tid >> 5;
    const int g    = lane >> 2;
    const int c    = lane & 3;
    const int wm0  = (warp & 3) * 32;
    const int wn0  = (warp >> 2) * 64;

    const int grp = lane >> 3, rin = lane & 7;
    uint32_t aoff[2], boff[4];
#pragma unroll
    for (int mi = 0; mi < 2; mi++)
        aoff[mi] = (uint32_t)(((wm0 + mi * 16 + (grp & 1) * 8 + rin) * SLDH
                               + (grp >> 1) * 8) * 2);
#pragma unroll
    for (int p = 0; p < 4; p++)
        boff[p] = (uint32_t)(A_BYTES + ((wn0 + p * 16 + (grp >> 1) * 8 + rin) * SLDH
                                        + (grp & 1) * 8) * 2);

    for (;;) {
        if (tid == 0) {
            int u = atomicAdd(&g_unit_ctr, 1);
            uinfo[0] = u;
            if (u < g_units_total) {
                int nt = u & (NT - 1);
                int mu = u >> 2;
                int e = 0;
                while (mu >= g_mtp[e + 1]) e++;
                uinfo[1] = e;
                uinfo[2] = (mu - g_mtp[e]) * TM;
                uinfo[3] = nt * TN;
                uinfo[4] = g_offsets[e];
                uinfo[5] = g_counts[e];
            }
        }
        __syncthreads();
        if (uinfo[0] >= g_units_total) break;
        const int e = uinfo[1], m0 = uinfo[2], n0 = uinfo[3];
        const int base = uinfo[4], cnt = uinfo[5];

        const __half* aP;
        const __half* bP[2];
        uint32_t offA, offB[2];
        {
            int r = tid >> 2, c4 = tid & 3;
            offA = (uint32_t)(r * 80 + c4 * 16);
            int m = m0 + r; if (m > cnt - 1) m = cnt - 1;
            aP = g_tokh + ((size_t)g_tok[base + m] << 10) + c4 * 8;
#pragma unroll
            for (int j = 0; j < 2; j++) {
                int id = tid + j * 512;
                int rb = id >> 2, cb = id & 3;
                offB[j] = (uint32_t)(A_BYTES + rb * 80 + cb * 16);
                bP[j] = g_wh + ((size_t)e << 20) + ((size_t)(n0 + rb) << 10) + cb * 8;
            }
        }

        auto issue_copy = [&](int kt) {
            uint32_t sb = sbase + (uint32_t)(kt % NSTAGE) * STAGE_BYTES;
            int ko = kt * TK;
            cpa16(sb + offA, aP + ko);
            cpa16(sb + offB[0], bP[0] + ko);
            cpa16(sb + offB[1], bP[1] + ko);
            asm volatile("cp.async.commit_group;\n" ::: "memory");
        };

        float acc[2][8][4];
#pragma unroll
        for (int mi = 0; mi < 2; mi++)
#pragma unroll
            for (int ni = 0; ni < 8; ni++)
#pragma unroll
                for (int r = 0; r < 4; r++) acc[mi][ni][r] = 0.f;

        auto compute = [&](int kt) {
            const uint32_t stg = sbase + (uint32_t)(kt % NSTAGE) * STAGE_BYTES;
#pragma unroll
            for (int ks = 0; ks < 2; ks++) {
                const uint32_t kb = (uint32_t)(ks * 32);
                uint32_t a[2][4];
#pragma unroll
                for (int mi = 0; mi < 2; mi++)
                    ldsm4(a[mi][0], a[mi][1], a[mi][2], a[mi][3], stg + aoff[mi] + kb);
#pragma unroll
                for (int p = 0; p < 4; p++) {
                    uint32_t b0, b1, b2, b3;
                    ldsm4(b0, b1, b2, b3, stg + boff[p] + kb);
#pragma unroll
                    for (int mi = 0; mi < 2; mi++) {
                        float* d0 = acc[mi][p * 2];
                        float* d1 = acc[mi][p * 2 + 1];
                        asm volatile(
                            "mma.sync.aligned.m16n8k16.row.col.f32.f16.f16.f32 "
                            "{%0,%1,%2,%3},{%4,%5,%6,%7},{%8,%9},{%0,%1,%2,%3};\n"
                            : "+f"(d0[0]), "+f"(d0[1]), "+f"(d0[2]), "+f"(d0[3])
                            : "r"(a[mi][0]), "r"(a[mi][1]), "r"(a[mi][2]), "r"(a[mi][3]),
                              "r"(b0), "r"(b1));
                        asm volatile(
                            "mma.sync.aligned.m16n8k16.row.col.f32.f16.f16.f32 "
                            "{%0,%1,%2,%3},{%4,%5,%6,%7},{%8,%9},{%0,%1,%2,%3};\n"
                            : "+f"(d1[0]), "+f"(d1[1]), "+f"(d1[2]), "+f"(d1[3])
                            : "r"(a[mi][0]), "r"(a[mi][1]), "r"(a[mi][2]), "r"(a[mi][3]),
                              "r"(b2), "r"(b3));
                    }
                }
            }
        };

        issue_copy(0); issue_copy(1); issue_copy(2); issue_copy(3);

        for (int kt = 0; kt < KTILES; kt += 2) {
            if (kt <= KTILES - 4)
                asm volatile("cp.async.wait_group 2;\n" ::: "memory");
            else
                asm volatile("cp.async.wait_group 0;\n" ::: "memory");
            __syncthreads();
            if (kt + 5 < KTILES) { issue_copy(kt + 4); issue_copy(kt + 5); }
            compute(kt);
            compute(kt + 1);
        }

        // epilogue: relu(acc + bias) -> fp16 staging
        float2 bias2[8];
#pragma unroll
        for (int ni = 0; ni < 8; ni++) {
            int n = n0 + wn0 + ni * 8 + 2 * c;
            bias2[ni] = *(const float2*)(expert_b + (size_t)e * HDIM + n);
        }
#pragma unroll
        for (int mi = 0; mi < 2; mi++) {
#pragma unroll
            for (int half = 0; half < 2; half++) {
                int m = m0 + wm0 + mi * 16 + g + half * 8;
                if (m < cnt) {
                    __half* orow = g_staging + (size_t)(base + m) * HDIM + n0 + wn0 + 2 * c;
#pragma unroll
                    for (int ni = 0; ni < 8; ni++) {
                        float v0 = fmaxf(acc[mi][ni][half * 2 + 0] + bias2[ni].x, 0.f);
                        float v1 = fmaxf(acc[mi][ni][half * 2 + 1] + bias2[ni].y, 0.f);
                        __half2 h = __floats2half2_rn(v0, v1);
                        *(uint32_t*)(orow + ni * 8) = *(uint32_t*)&h;
                    }
                }
            }
        }
    }
}

// ---------- combine (fp16 staging -> fp32 out) ----------
__global__ void combine_kernel(float* __restrict__ out) {
    const int n = blockIdx.x;
    const int s0 = g_slot[n * 2], s1 = g_slot[n * 2 + 1];
    const float w0 = g_top2_w[n * 2], w1 = g_top2_w[n * 2 + 1];
    const __half2* a = (const __half2*)(g_staging + (size_t)s0 * HDIM);
    const __half2* b = (const __half2*)(g_staging + (size_t)s1 * HDIM);
    float2* o = (float2*)(out + (size_t)n * HDIM);
    for (int i = threadIdx.x; i < HDIM / 2; i += blockDim.x) {
        float2 x = __half22float2(a[i]);
        float2 y = __half22float2(b[i]);
        o[i] = make_float2(w0 * x.x + w1 * y.x, w0 * x.y + w1 * y.y);
    }
}

extern "C" void kernel_launch(void* const* d_in, const int* in_sizes, int n_in,
                              void* d_out, int out_size) {
    const float* tokens   = (const float*)d_in[0];
    const float* gate_w   = (const float*)d_in[1];
    const float* expert_w = (const float*)d_in[2];
    const float* expert_b = (const float*)d_in[3];
    float* out = (float*)d_out;

    cudaFuncSetAttribute(moe_gemm_kernel,
                         cudaFuncAttributeMaxDynamicSharedMemorySize, SMEM_TOTAL);

    prep_kernel<<<NGATE + NCONV, 512>>>(tokens, gate_w, expert_w);
    route_kernel<<<1, 512>>>();
    moe_gemm_kernel<<<148, 512, SMEM_TOTAL>>>(expert_b);
    combine_kernel<<<N_TOK, 256>>>(out);
}